// round 16
// baseline (speedup 1.0000x reference)
#include <cuda_runtime.h>

// Problem constants (fixed by setup_inputs)
#define BB 4
#define LL 256
#define DMM 256
#define DLL 64
#define RRR 256
#define NROWS 1024

// ---------------------------------------------------------------------------
// Scratch (device globals — no allocation allowed)
// ---------------------------------------------------------------------------
__device__ float g_qz[NROWS * DMM];       // masked softmax(x)
__device__ float g_up[128 * DMM];         // per-8-row-slab column partials
__device__ float g_Mpart[8 * DMM * DMM];  // Mp partials: p = q*2 + t
__device__ float g_M[DMM * DMM];          // summed M
__device__ float g_F[2 * NROWS * DMM];    // F partials by K-half
__device__ unsigned int g_bar;            // generation barrier (zero-init)

__device__ __forceinline__ void grid_barrier(int tid) {
    __threadfence();
    __syncthreads();
    if (tid == 0) {
        unsigned old = atomicAdd(&g_bar, 1u);
        unsigned target = (old & ~127u) + 128u;  // counter is a multiple of
        volatile unsigned* vb = &g_bar;          // 128 at each barrier entry
        while (*vb < target) { }
    }
    __syncthreads();
    __threadfence();
}

// ---------------------------------------------------------------------------
// Single fused kernel, grid 128 x 256 threads (all blocks co-resident).
// ---------------------------------------------------------------------------
__global__ __launch_bounds__(256) void k_all(const float* __restrict__ x,
                                             const int* __restrict__ mask,
                                             const float* __restrict__ U,
                                             const float* __restrict__ V,
                                             const float* __restrict__ W,
                                             float* __restrict__ out) {
    // smem pool (floats), overlaid per phase:
    //  1a: sm[8][256]                        @0      (2048)
    //  1b: As[2][32][68] @0 (4352) | Bs[2][32][68] @4352 (4352)
    //      sWs[64] @8704 | swp[256] @8768
    //  2 : As2[2][32][68] @0 (4352) | Bs2[2][32][64] @4352 (4096) | us @8448
    __shared__ __align__(16) float pool[9024];
    const int tid = threadIdx.x;
    const int bx  = blockIdx.x;

    // ================= Phase 1a: softmax + u-partials =================
    {
        float (*sm)[256] = (float (*)[256])pool;
        const int wid = tid >> 5, lane = tid & 31;
        const int row = bx * 8 + wid;

        const float4* xr = (const float4*)(x + row * DMM);
        float4 v0 = xr[lane];
        float4 v1 = xr[lane + 32];

        float m = fmaxf(fmaxf(fmaxf(v0.x, v0.y), fmaxf(v0.z, v0.w)),
                        fmaxf(fmaxf(v1.x, v1.y), fmaxf(v1.z, v1.w)));
        #pragma unroll
        for (int off = 16; off > 0; off >>= 1)
            m = fmaxf(m, __shfl_xor_sync(0xFFFFFFFFu, m, off));

        float4 e0 = make_float4(__expf(v0.x - m), __expf(v0.y - m),
                                __expf(v0.z - m), __expf(v0.w - m));
        float4 e1 = make_float4(__expf(v1.x - m), __expf(v1.y - m),
                                __expf(v1.z - m), __expf(v1.w - m));

        float s = e0.x + e0.y + e0.z + e0.w + e1.x + e1.y + e1.z + e1.w;
        #pragma unroll
        for (int off = 16; off > 0; off >>= 1)
            s += __shfl_xor_sync(0xFFFFFFFFu, s, off);

        float sc = (mask[row] != 0) ? (1.0f / s) : 0.0f;
        float4 q0 = make_float4(e0.x * sc, e0.y * sc, e0.z * sc, e0.w * sc);
        float4 q1 = make_float4(e1.x * sc, e1.y * sc, e1.z * sc, e1.w * sc);

        float4* qr = (float4*)(g_qz + row * DMM);
        qr[lane]      = q0;
        qr[lane + 32] = q1;

        *(float4*)&sm[wid][lane * 4]       = q0;
        *(float4*)&sm[wid][128 + lane * 4] = q1;
        __syncthreads();

        float p = 0.0f;
        #pragma unroll
        for (int w = 0; w < 8; w++) p += sm[w][tid];
        g_up[bx * DMM + tid] = p;
    }
    __syncthreads();   // pool reuse

    // ======= Phase 1b: Mp partial tile, 64x64 x K=64, 4x4 acc =======
    // bx -> q = bx>>5 (K quarter), r = bx&31: t = r>>4, b0, a0
    {
        float (*As)[32][68] = (float (*)[32][68])pool;          // @0
        float (*Bs)[32][68] = (float (*)[32][68])(pool + 4352); // @4352
        float* sWs = pool + 8704;   // 64
        float* swp = pool + 8768;   // 256

        const int q  = bx >> 5;
        const int r  = bx & 31;
        const int t  = r >> 4;
        const int b0 = ((r >> 2) & 3) * 64;
        const int a0 = (r & 3) * 64;
        const int kbase = q * 64;
        const float* Vt = V + t * (DMM * RRR);
        const float* Ut = U + t * (DMM * RRR);

        {   // sW for d in [kbase, kbase+64): 4-way c-split then combine
            int dl = tid & 63, cq = tid >> 6;
            const float* w = W + t * DLL * RRR + (cq * 16) * RRR + kbase + dl;
            float s = 0.0f;
            #pragma unroll
            for (int c = 0; c < 16; c++) s += w[c * RRR];
            swp[tid] = s;
        }
        __syncthreads();
        if (tid < 64)
            sWs[tid] = (swp[tid] + swp[64 + tid] + swp[128 + tid] + swp[192 + tid])
                       * (1.0f / 64.0f);
        __syncthreads();

        const int l_kk = tid & 31, l_rr = tid >> 5;   // loads: +8 per p (8 ps)
        const int tx = tid & 15, ty = tid >> 4;       // compute: 4x4 acc

        float acc[4][4] = {};
        float ar[8], br[8];

        // prologue: k-block 0
        #pragma unroll
        for (int p = 0; p < 8; p++) {
            ar[p] = Vt[(b0 + l_rr + 8 * p) * RRR + kbase + l_kk];
            br[p] = Ut[(a0 + l_rr + 8 * p) * RRR + kbase + l_kk];
        }
        #pragma unroll
        for (int p = 0; p < 8; p++) {
            As[0][l_kk][l_rr + 8 * p] = ar[p] * sWs[l_kk];
            Bs[0][l_kk][l_rr + 8 * p] = br[p];
        }
        __syncthreads();

        int buf = 0;
        #pragma unroll
        for (int kb = 0; kb < 2; kb++) {
            if (kb < 1) {
                #pragma unroll
                for (int p = 0; p < 8; p++) {
                    ar[p] = Vt[(b0 + l_rr + 8 * p) * RRR + kbase + 32 + l_kk];
                    br[p] = Ut[(a0 + l_rr + 8 * p) * RRR + kbase + 32 + l_kk];
                }
            }
            #pragma unroll
            for (int k2 = 0; k2 < 32; k2++) {
                float4 a = *(const float4*)&As[buf][k2][ty * 4];
                float4 b = *(const float4*)&Bs[buf][k2][tx * 4];
                float av[4] = {a.x, a.y, a.z, a.w};
                float bv[4] = {b.x, b.y, b.z, b.w};
                #pragma unroll
                for (int i = 0; i < 4; i++)
                    #pragma unroll
                    for (int j = 0; j < 4; j++)
                        acc[i][j] = fmaf(av[i], bv[j], acc[i][j]);
            }
            if (kb < 1) {
                #pragma unroll
                for (int p = 0; p < 8; p++) {
                    As[buf ^ 1][l_kk][l_rr + 8 * p] = ar[p] * sWs[32 + l_kk];
                    Bs[buf ^ 1][l_kk][l_rr + 8 * p] = br[p];
                }
                __syncthreads();
                buf ^= 1;
            }
        }

        float* dst = g_Mpart + ((q << 1) | t) * (DMM * DMM);
        #pragma unroll
        for (int i = 0; i < 4; i++) {
            float4 v4 = make_float4(acc[i][0], acc[i][1], acc[i][2], acc[i][3]);
            *(float4*)&dst[(b0 + ty * 4 + i) * DMM + a0 + tx * 4] = v4;
        }
    }

    grid_barrier(tid);

    // ================= Red: g_M = sum of 8 partials =================
    {
        int e = (bx * 256 + tid) * 2;     // 2 floats per thread
        float2 s2 = make_float2(0.0f, 0.0f);
        #pragma unroll
        for (int p = 0; p < 8; p++) {
            float2 v = *(const float2*)&g_Mpart[p * (DMM * DMM) + e];
            s2.x += v.x; s2.y += v.y;
        }
        *(float2*)&g_M[e] = s2;
    }

    grid_barrier(tid);

    // ======= Phase 2: F partial tile, 64x64 x K=128, 4x4 acc =======
    // bx -> kh = bx>>6 (K half), r = bx&63: m0 = (r>>2)*64, a0 = (r&3)*64
    {
        float (*As2)[32][68] = (float (*)[32][68])pool;           // @0
        float (*Bs2)[32][64] = (float (*)[32][64])(pool + 4352);  // @4352
        float* us = pool + 8448;                                  // 256

        const int kh = bx >> 6;
        const int r  = bx & 63;
        const int m0 = (r >> 2) * 64;
        const int a0 = (r & 3) * 64;
        const int z  = m0 >> 8;
        const int kbase = kh * 128;

        {
            const float* up = g_up + z * 32 * DMM + tid;
            float au = 0.0f;
            #pragma unroll
            for (int s = 0; s < 32; s++) au += up[s * DMM];
            us[tid] = au;
        }
        __syncthreads();

        const int a_kk = tid & 31, a_mm = tid >> 5;   // A: +8 per p (8 ps)
        const int b_aa = tid & 63, b_kk = tid >> 6;   // B: +4 per p (8 ps)
        const int tx = tid & 15, ty = tid >> 4;

        float acc[4][4] = {};
        float ar[8], brM[8];

        // prologue: k-block 0
        #pragma unroll
        for (int p = 0; p < 8; p++)
            ar[p] = g_qz[(m0 + a_mm + 8 * p) * DMM + kbase + a_kk];
        #pragma unroll
        for (int p = 0; p < 8; p++)
            brM[p] = g_M[(kbase + b_kk + 4 * p) * DMM + a0 + b_aa];
        #pragma unroll
        for (int p = 0; p < 8; p++)
            As2[0][a_kk][a_mm + 8 * p] = us[kbase + a_kk] - ar[p];
        #pragma unroll
        for (int p = 0; p < 8; p++)
            Bs2[0][b_kk + 4 * p][b_aa] = brM[p];
        __syncthreads();

        int buf = 0;
        #pragma unroll
        for (int kb = 0; kb < 4; kb++) {
            const int kn = kbase + (kb + 1) * 32;
            if (kb < 3) {
                #pragma unroll
                for (int p = 0; p < 8; p++)
                    ar[p] = g_qz[(m0 + a_mm + 8 * p) * DMM + kn + a_kk];
                #pragma unroll
                for (int p = 0; p < 8; p++)
                    brM[p] = g_M[(kn + b_kk + 4 * p) * DMM + a0 + b_aa];
            }
            #pragma unroll
            for (int k2 = 0; k2 < 32; k2++) {
                float4 a = *(const float4*)&As2[buf][k2][ty * 4];
                float4 b = *(const float4*)&Bs2[buf][k2][tx * 4];
                float av[4] = {a.x, a.y, a.z, a.w};
                float bv[4] = {b.x, b.y, b.z, b.w};
                #pragma unroll
                for (int i = 0; i < 4; i++)
                    #pragma unroll
                    for (int j = 0; j < 4; j++)
                        acc[i][j] = fmaf(av[i], bv[j], acc[i][j]);
            }
            if (kb < 3) {
                #pragma unroll
                for (int p = 0; p < 8; p++)
                    As2[buf ^ 1][a_kk][a_mm + 8 * p] = us[kn + a_kk] - ar[p];
                #pragma unroll
                for (int p = 0; p < 8; p++)
                    Bs2[buf ^ 1][b_kk + 4 * p][b_aa] = brM[p];
                __syncthreads();
                buf ^= 1;
            }
        }

        float* dst = g_F + kh * (NROWS * DMM);
        #pragma unroll
        for (int i = 0; i < 4; i++) {
            float4 v4 = make_float4(acc[i][0], acc[i][1], acc[i][2], acc[i][3]);
            *(float4*)&dst[(m0 + ty * 4 + i) * DMM + a0 + tx * 4] = v4;
        }
    }

    grid_barrier(tid);

    // ================= Phase 3: out = x + mask*(F0+F1) =================
    {
        #pragma unroll
        for (int h = 0; h < 2; h++) {
            int idx = bx * 2048 + h * 1024 + tid * 4;
            int row = idx >> 8;
            float mv = (mask[row] != 0) ? 1.0f : 0.0f;
            float4 f0 = *(const float4*)&g_F[idx];
            float4 f1 = *(const float4*)&g_F[NROWS * DMM + idx];
            float4 xv = *(const float4*)&x[idx];
            float4 ov = make_float4(fmaf(mv, f0.x + f1.x, xv.x),
                                    fmaf(mv, f0.y + f1.y, xv.y),
                                    fmaf(mv, f0.z + f1.z, xv.z),
                                    fmaf(mv, f0.w + f1.w, xv.w));
            *(float4*)&out[idx] = ov;
        }
    }
}

// ---------------------------------------------------------------------------
// Launch — a single kernel node.
// Inputs (metadata order): x (f32, 262144), U (f32, 131072), V (f32, 131072),
//                          W (f32, 32768),  mask (i32, 1024)
// ---------------------------------------------------------------------------
extern "C" void kernel_launch(void* const* d_in, const int* in_sizes, int n_in,
                              void* d_out, int out_size) {
    (void)in_sizes; (void)n_in; (void)out_size;
    const float* x    = (const float*)d_in[0];
    const float* U    = (const float*)d_in[1];
    const float* V    = (const float*)d_in[2];
    const float* W    = (const float*)d_in[3];
    const int*   mask = (const int*)d_in[4];
    float* out = (float*)d_out;

    k_all<<<128, 256>>>(x, mask, U, V, W, out);
}

// round 17
// speedup vs baseline: 1.0960x; 1.0960x over previous
#include <cuda_runtime.h>

// Problem constants (fixed by setup_inputs)
#define BB 4
#define LL 256
#define DMM 256
#define DLL 64
#define RRR 256
#define NROWS 1024

// ---------------------------------------------------------------------------
// Scratch (device globals — no allocation allowed)
// ---------------------------------------------------------------------------
__device__ float g_qz[NROWS * DMM];        // masked softmax(x)
__device__ float g_up[256 * DMM];          // per-4-row-slab column partials
__device__ float g_Mpart[16 * DMM * DMM];  // Mp partials: p = t*8 + kq
__device__ float g_M[DMM * DMM];           // summed M
__device__ float g_F[4 * NROWS * DMM];     // F partials by K-quarter
__device__ unsigned int g_bar;             // generation barrier (zero-init)

__device__ __forceinline__ void grid_barrier(int tid) {
    __threadfence();
    __syncthreads();
    if (tid == 0) {
        unsigned old = atomicAdd(&g_bar, 1u);
        unsigned target = (old & ~255u) + 256u;  // counter is a multiple of
        volatile unsigned* vb = &g_bar;          // 256 at each barrier entry
        while (*vb < target) { }
    }
    __syncthreads();
    __threadfence();
}

// ---------------------------------------------------------------------------
// Single fused kernel, grid 256 x 256 threads, 2 blocks/SM co-resident.
// ---------------------------------------------------------------------------
__global__ void __launch_bounds__(256, 2)
k_all(const float* __restrict__ x,
      const int* __restrict__ mask,
      const float* __restrict__ U,
      const float* __restrict__ V,
      const float* __restrict__ W,
      float* __restrict__ out) {
    // smem pool (floats), overlaid per phase:
    //  1a: sm[4][256]                                   (1024)
    //  1b: As[32][68] @0 (2176) | Bs[32][68] @2176 (2176)
    //      sWs[32] @4352 | swp[256] @4384
    //  2 : As2[2][32][68] @0 (4352) | Bs2[2][32][64] @4352 (4096) | us @8448
    __shared__ __align__(16) float pool[8704];
    const int tid = threadIdx.x;
    const int bx  = blockIdx.x;

    // ================= Phase 1a: softmax (4 rows) + u-partials =================
    {
        float (*sm)[256] = (float (*)[256])pool;
        const int wid = tid >> 5, lane = tid & 31;

        if (wid < 4) {
            const int row = bx * 4 + wid;
            const float4* xr = (const float4*)(x + row * DMM);
            float4 v0 = xr[lane];
            float4 v1 = xr[lane + 32];

            float m = fmaxf(fmaxf(fmaxf(v0.x, v0.y), fmaxf(v0.z, v0.w)),
                            fmaxf(fmaxf(v1.x, v1.y), fmaxf(v1.z, v1.w)));
            #pragma unroll
            for (int off = 16; off > 0; off >>= 1)
                m = fmaxf(m, __shfl_xor_sync(0xFFFFFFFFu, m, off));

            float4 e0 = make_float4(__expf(v0.x - m), __expf(v0.y - m),
                                    __expf(v0.z - m), __expf(v0.w - m));
            float4 e1 = make_float4(__expf(v1.x - m), __expf(v1.y - m),
                                    __expf(v1.z - m), __expf(v1.w - m));

            float s = e0.x + e0.y + e0.z + e0.w + e1.x + e1.y + e1.z + e1.w;
            #pragma unroll
            for (int off = 16; off > 0; off >>= 1)
                s += __shfl_xor_sync(0xFFFFFFFFu, s, off);

            float sc = (mask[row] != 0) ? (1.0f / s) : 0.0f;
            float4 q0 = make_float4(e0.x * sc, e0.y * sc, e0.z * sc, e0.w * sc);
            float4 q1 = make_float4(e1.x * sc, e1.y * sc, e1.z * sc, e1.w * sc);

            float4* qr = (float4*)(g_qz + row * DMM);
            qr[lane]      = q0;
            qr[lane + 32] = q1;

            *(float4*)&sm[wid][lane * 4]       = q0;
            *(float4*)&sm[wid][128 + lane * 4] = q1;
        }
        __syncthreads();

        float p = sm[0][tid] + sm[1][tid] + sm[2][tid] + sm[3][tid];
        g_up[bx * DMM + tid] = p;
    }
    __syncthreads();   // pool reuse

    // ======= Phase 1b: Mp partial tile, 64x64 x K=32, 4x4 acc =======
    // bx: p = bx>>4 -> t = p>>3, kq = p&7; r = bx&15 -> b0, a0
    {
        float (*As)[68] = (float (*)[68])pool;            // @0
        float (*Bs)[68] = (float (*)[68])(pool + 2176);   // @2176
        float* sWs = pool + 4352;   // 32
        float* swp = pool + 4384;   // 256

        const int p_  = bx >> 4;
        const int t   = p_ >> 3;
        const int kq  = p_ & 7;
        const int r   = bx & 15;
        const int b0  = (r >> 2) * 64;
        const int a0  = (r & 3) * 64;
        const int kbase = kq * 32;
        const float* Vt = V + t * (DMM * RRR);
        const float* Ut = U + t * (DMM * RRR);

        {   // sW for d in [kbase, kbase+32): 8-way c-split then combine
            int dl = tid & 31, cg = tid >> 5;
            const float* w = W + t * DLL * RRR + (cg * 8) * RRR + kbase + dl;
            float s = 0.0f;
            #pragma unroll
            for (int c = 0; c < 8; c++) s += w[c * RRR];
            swp[tid] = s;
        }
        __syncthreads();
        if (tid < 32) {
            float s = 0.0f;
            #pragma unroll
            for (int g = 0; g < 8; g++) s += swp[g * 32 + tid];
            sWs[tid] = s * (1.0f / 64.0f);
        }

        const int l_kk = tid & 31, l_rr = tid >> 5;   // loads: +8 per p (8 ps)
        const int tx = tid & 15, ty = tid >> 4;       // compute: 4x4 acc

        float ar[8], br[8];
        #pragma unroll
        for (int p = 0; p < 8; p++) {
            ar[p] = Vt[(b0 + l_rr + 8 * p) * RRR + kbase + l_kk];
            br[p] = Ut[(a0 + l_rr + 8 * p) * RRR + kbase + l_kk];
        }
        __syncthreads();   // sWs ready
        #pragma unroll
        for (int p = 0; p < 8; p++) {
            As[l_kk][l_rr + 8 * p] = ar[p] * sWs[l_kk];
            Bs[l_kk][l_rr + 8 * p] = br[p];
        }
        __syncthreads();

        float acc[4][4] = {};
        #pragma unroll
        for (int k2 = 0; k2 < 32; k2++) {
            float4 a = *(const float4*)&As[k2][ty * 4];
            float4 b = *(const float4*)&Bs[k2][tx * 4];
            float av[4] = {a.x, a.y, a.z, a.w};
            float bv[4] = {b.x, b.y, b.z, b.w};
            #pragma unroll
            for (int i = 0; i < 4; i++)
                #pragma unroll
                for (int j = 0; j < 4; j++)
                    acc[i][j] = fmaf(av[i], bv[j], acc[i][j]);
        }

        float* dst = g_Mpart + p_ * (DMM * DMM);
        #pragma unroll
        for (int i = 0; i < 4; i++) {
            float4 v4 = make_float4(acc[i][0], acc[i][1], acc[i][2], acc[i][3]);
            *(float4*)&dst[(b0 + ty * 4 + i) * DMM + a0 + tx * 4] = v4;
        }
    }

    grid_barrier(tid);

    // ================= Red: g_M = sum of 16 partials =================
    {
        int e = bx * 256 + tid;           // 65536 threads, 1 float each
        float s = 0.0f;
        #pragma unroll
        for (int p = 0; p < 16; p++) s += g_Mpart[p * (DMM * DMM) + e];
        g_M[e] = s;
    }

    grid_barrier(tid);

    // ======= Phase 2: F partial tile, 64x64 x K=64, 4x4 acc, dbuf =======
    // bx: kq2 = bx>>6 (K quarter), r = bx&63: m0 = (r>>2)*64, a0 = (r&3)*64
    {
        float (*As2)[32][68] = (float (*)[32][68])pool;           // @0
        float (*Bs2)[32][64] = (float (*)[32][64])(pool + 4352);  // @4352
        float* us = pool + 8448;                                  // 256

        const int kq2 = bx >> 6;
        const int r   = bx & 63;
        const int m0  = (r >> 2) * 64;
        const int a0  = (r & 3) * 64;
        const int z   = m0 >> 8;
        const int kbase = kq2 * 64;

        {
            const float* up = g_up + z * 64 * DMM + tid;
            float au = 0.0f;
            #pragma unroll
            for (int s = 0; s < 64; s++) au += up[s * DMM];
            us[tid] = au;
        }
        __syncthreads();

        const int a_kk = tid & 31, a_mm = tid >> 5;   // A: +8 per p (8 ps)
        const int b_aa = tid & 63, b_kk = tid >> 6;   // B: +4 per p (8 ps)
        const int tx = tid & 15, ty = tid >> 4;

        float acc[4][4] = {};
        float ar[8], brM[8];

        // prologue: k-block 0
        #pragma unroll
        for (int p = 0; p < 8; p++)
            ar[p] = g_qz[(m0 + a_mm + 8 * p) * DMM + kbase + a_kk];
        #pragma unroll
        for (int p = 0; p < 8; p++)
            brM[p] = g_M[(kbase + b_kk + 4 * p) * DMM + a0 + b_aa];
        #pragma unroll
        for (int p = 0; p < 8; p++)
            As2[0][a_kk][a_mm + 8 * p] = us[kbase + a_kk] - ar[p];
        #pragma unroll
        for (int p = 0; p < 8; p++)
            Bs2[0][b_kk + 4 * p][b_aa] = brM[p];
        __syncthreads();

        int buf = 0;
        #pragma unroll
        for (int kb = 0; kb < 2; kb++) {
            const int kn = kbase + 32;
            if (kb < 1) {
                #pragma unroll
                for (int p = 0; p < 8; p++)
                    ar[p] = g_qz[(m0 + a_mm + 8 * p) * DMM + kn + a_kk];
                #pragma unroll
                for (int p = 0; p < 8; p++)
                    brM[p] = g_M[(kn + b_kk + 4 * p) * DMM + a0 + b_aa];
            }
            #pragma unroll
            for (int k2 = 0; k2 < 32; k2++) {
                float4 a = *(const float4*)&As2[buf][k2][ty * 4];
                float4 b = *(const float4*)&Bs2[buf][k2][tx * 4];
                float av[4] = {a.x, a.y, a.z, a.w};
                float bv[4] = {b.x, b.y, b.z, b.w};
                #pragma unroll
                for (int i = 0; i < 4; i++)
                    #pragma unroll
                    for (int j = 0; j < 4; j++)
                        acc[i][j] = fmaf(av[i], bv[j], acc[i][j]);
            }
            if (kb < 1) {
                #pragma unroll
                for (int p = 0; p < 8; p++)
                    As2[buf ^ 1][a_kk][a_mm + 8 * p] = us[kn + a_kk] - ar[p];
                #pragma unroll
                for (int p = 0; p < 8; p++)
                    Bs2[buf ^ 1][b_kk + 4 * p][b_aa] = brM[p];
                __syncthreads();
                buf ^= 1;
            }
        }

        float* dst = g_F + kq2 * (NROWS * DMM);
        #pragma unroll
        for (int i = 0; i < 4; i++) {
            float4 v4 = make_float4(acc[i][0], acc[i][1], acc[i][2], acc[i][3]);
            *(float4*)&dst[(m0 + ty * 4 + i) * DMM + a0 + tx * 4] = v4;
        }
    }

    grid_barrier(tid);

    // ================= Phase 3: out = x + mask*(F0+F1+F2+F3) =================
    {
        int idx = bx * 1024 + tid * 4;
        int row = idx >> 8;
        float mv = (mask[row] != 0) ? 1.0f : 0.0f;
        float4 f0 = *(const float4*)&g_F[idx];
        float4 f1 = *(const float4*)&g_F[NROWS * DMM + idx];
        float4 f2 = *(const float4*)&g_F[2 * NROWS * DMM + idx];
        float4 f3 = *(const float4*)&g_F[3 * NROWS * DMM + idx];
        float4 xv = *(const float4*)&x[idx];
        float4 ov = make_float4(fmaf(mv, (f0.x + f1.x) + (f2.x + f3.x), xv.x),
                                fmaf(mv, (f0.y + f1.y) + (f2.y + f3.y), xv.y),
                                fmaf(mv, (f0.z + f1.z) + (f2.z + f3.z), xv.z),
                                fmaf(mv, (f0.w + f1.w) + (f2.w + f3.w), xv.w));
        *(float4*)&out[idx] = ov;
    }
}

// ---------------------------------------------------------------------------
// Launch — a single kernel node.
// Inputs (metadata order): x (f32, 262144), U (f32, 131072), V (f32, 131072),
//                          W (f32, 32768),  mask (i32, 1024)
// ---------------------------------------------------------------------------
extern "C" void kernel_launch(void* const* d_in, const int* in_sizes, int n_in,
                              void* d_out, int out_size) {
    (void)in_sizes; (void)n_in; (void)out_size;
    const float* x    = (const float*)d_in[0];
    const float* U    = (const float*)d_in[1];
    const float* V    = (const float*)d_in[2];
    const float* W    = (const float*)d_in[3];
    const int*   mask = (const int*)d_in[4];
    float* out = (float*)d_out;

    k_all<<<256, 256>>>(x, mask, U, V, W, out);
}